// round 1
// baseline (speedup 1.0000x reference)
#include <cuda_runtime.h>

// KPConv fused kernel for GB300 (sm_103a).
//
// out[m,c] = sum_{k,f} agg[m,k,f] * kv[k,f,c]
// agg[m,k,f] = sum_{edges e with segment_ids[e]==m} w[e,k] * features[nbr[e],f]
// w[e,k] = max(0, 1 - ||(points[nbr[e]] - output_points[m]) - k_points[k]|| / EXTENT)
//
// Strategy: block handles ROWS=16 consecutive output points (segment_ids sorted
// -> contiguous edge ranges found by binary search). Phase 1: warp-per-row
// aggregation, lane = feature channel, per-k weights broadcast via shfl,
// K accumulators in registers (no atomics). Phase 2: register-tiled
// [16 x 480] x [480 x 64] fp32 GEMM, kv streamed via float4 (hot in L1/L2).

#define KP      15
#define FDIM    32
#define CDIM    64
#define ROWS    16
#define AGG_LD  484              // 480 padded to break bank alignment (484*4 % 16 == 0)
#define KFTOT   (KP * FDIM)      // 480
#define INV_EXTENT (1.0f / 0.6f)

__global__ __launch_bounds__(128) void kpconv_fused_kernel(
    const float* __restrict__ points,        // [N,3]
    const float* __restrict__ features,      // [N,32]
    const float* __restrict__ outp,          // [M,3]
    const int*   __restrict__ nbr,           // [E]
    const int*   __restrict__ sid,           // [E] sorted
    const float* __restrict__ kpts,          // [15,3]
    const float* __restrict__ kv,            // [15,32,64]
    float*       __restrict__ out,           // [M,64]
    int M, int E)
{
    __shared__ float agg_s[ROWS * AGG_LD];
    __shared__ int   bound[ROWS + 1];
    __shared__ float kp[KP * 3];

    const int tid = threadIdx.x;
    const int m0  = blockIdx.x * ROWS;

    // kernel points into shared
    if (tid < KP * 3) kp[tid] = kpts[tid];

    // per-row edge ranges: lower_bound over sorted segment_ids
    if (tid <= ROWS) {
        int target = m0 + tid;
        int lo = 0, hi = E;
        while (lo < hi) {
            int mid = (lo + hi) >> 1;
            if (__ldg(sid + mid) < target) lo = mid + 1; else hi = mid;
        }
        bound[tid] = lo;
    }

    // zero agg tile
    for (int i = tid; i < ROWS * AGG_LD; i += 128) agg_s[i] = 0.f;
    __syncthreads();

    const int warp = tid >> 5;
    const int lane = tid & 31;

    // ---------------- Phase 1: aggregation (warp-per-row) ----------------
    for (int r = warp; r < ROWS; r += 4) {
        int m = m0 + r;
        if (m >= M) break;
        int s = bound[r];
        int e = bound[r + 1];

        float ox = __ldg(outp + m * 3 + 0);
        float oy = __ldg(outp + m * 3 + 1);
        float oz = __ldg(outp + m * 3 + 2);

        float kx = 0.f, ky = 0.f, kz = 0.f;
        if (lane < KP) {
            kx = kp[lane * 3 + 0];
            ky = kp[lane * 3 + 1];
            kz = kp[lane * 3 + 2];
        }

        float acc[KP];
        #pragma unroll
        for (int k = 0; k < KP; k++) acc[k] = 0.f;

        for (int ei = s; ei < e; ++ei) {
            int ni = __ldg(nbr + ei);
            // lane = feature channel: coalesced 128B gather
            float feat = __ldg(features + ni * FDIM + lane);
            float rx = __ldg(points + ni * 3 + 0) - ox;
            float ry = __ldg(points + ni * 3 + 1) - oy;
            float rz = __ldg(points + ni * 3 + 2) - oz;

            // lane k < 15 computes weight for kernel point k
            float dx = rx - kx, dy = ry - ky, dz = rz - kz;
            float sq = fmaf(dx, dx, fmaf(dy, dy, dz * dz));
            float w  = fmaxf(1.f - sqrtf(sq) * INV_EXTENT, 0.f);

            #pragma unroll
            for (int k = 0; k < KP; k++) {
                float wk = __shfl_sync(0xffffffffu, w, k);
                acc[k] = fmaf(wk, feat, acc[k]);
            }
        }

        #pragma unroll
        for (int k = 0; k < KP; k++)
            agg_s[r * AGG_LD + k * 32 + lane] = acc[k];
    }
    __syncthreads();

    // ---------------- Phase 2: GEMM [ROWS,480] x [480,64] ----------------
    // 128 threads: rg = tid/16 (8 groups x 2 rows), cg = tid%16 (x 4 cols)
    const int rg = tid >> 4;
    const int cg = tid & 15;

    float accc[2][4];
    #pragma unroll
    for (int i = 0; i < 2; i++)
        #pragma unroll
        for (int j = 0; j < 4; j++) accc[i][j] = 0.f;

    const float* kvp = kv + (cg << 2);

    #pragma unroll 2
    for (int kf = 0; kf < KFTOT; kf += 4) {
        float a[2][4];
        #pragma unroll
        for (int i = 0; i < 2; i++)
            *(float4*)a[i] = *(const float4*)&agg_s[(rg * 2 + i) * AGG_LD + kf];

        #pragma unroll
        for (int j = 0; j < 4; j++) {
            float4 b = *(const float4*)(kvp + (kf + j) * CDIM);
            #pragma unroll
            for (int i = 0; i < 2; i++) {
                accc[i][0] = fmaf(a[i][j], b.x, accc[i][0]);
                accc[i][1] = fmaf(a[i][j], b.y, accc[i][1]);
                accc[i][2] = fmaf(a[i][j], b.z, accc[i][2]);
                accc[i][3] = fmaf(a[i][j], b.w, accc[i][3]);
            }
        }
    }

    #pragma unroll
    for (int i = 0; i < 2; i++) {
        int m = m0 + rg * 2 + i;
        if (m < M)
            *(float4*)(out + m * CDIM + (cg << 2)) =
                make_float4(accc[i][0], accc[i][1], accc[i][2], accc[i][3]);
    }
}

extern "C" void kernel_launch(void* const* d_in, const int* in_sizes, int n_in,
                              void* d_out, int out_size) {
    const float* points   = (const float*)d_in[0];
    const float* features = (const float*)d_in[1];
    const float* outp     = (const float*)d_in[2];
    const int*   nbr      = (const int*)d_in[3];
    const int*   sid      = (const int*)d_in[4];
    const float* kpts     = (const float*)d_in[5];
    const float* kv       = (const float*)d_in[6];
    float*       out      = (float*)d_out;

    int E = in_sizes[3];
    int M = out_size / CDIM;
    int blocks = (M + ROWS - 1) / ROWS;

    kpconv_fused_kernel<<<blocks, 128>>>(points, features, outp, nbr, sid,
                                         kpts, kv, out, M, E);
}

// round 2
// speedup vs baseline: 1.0610x; 1.0610x over previous
#include <cuda_runtime.h>

// KPConv fused kernel for GB300 (sm_103a). Round 2.
//
// out[m,c] = sum_{k,f} agg[m,k,f] * kv[k,f,c]
// agg[m,k,f] = sum_{edges e in segment m} w[e,k] * features[nbr[e],f]
//
// R2 changes vs R1 (L1/latency-bound per ncu):
//  - Aggregation: per-lane batch-load of 32 neighbor indices (kills the
//    nbr->feat dependent chain), 4-edge unroll for MLP~16 on gathers.
//  - ROWS 16->32 with 256 threads + dynamic smem: halves kv L1 traffic
//    in the GEMM phase.

#define KP      15
#define FDIM    32
#define CDIM    64
#define ROWS    32
#define NWARP   8
#define THREADS 256
#define AGG_LD  484              // 480 padded; 484*4 % 16 == 0 keeps float4 alignment
#define KFTOT   (KP * FDIM)      // 480
#define INV_EXTENT (1.0f / 0.6f)
#define SMEM_BYTES (ROWS * AGG_LD * 4)

__global__ __launch_bounds__(THREADS, 3) void kpconv_fused_kernel(
    const float* __restrict__ points,        // [N,3]
    const float* __restrict__ features,      // [N,32]
    const float* __restrict__ outp,          // [M,3]
    const int*   __restrict__ nbr,           // [E]
    const int*   __restrict__ sid,           // [E] sorted
    const float* __restrict__ kpts,          // [15,3]
    const float* __restrict__ kv,            // [15,32,64]
    float*       __restrict__ out,           // [M,64]
    int M, int E)
{
    extern __shared__ float agg_s[];         // [ROWS * AGG_LD]
    __shared__ int   bound[ROWS + 1];
    __shared__ float kp[KP * 3];

    const int tid = threadIdx.x;
    const int m0  = blockIdx.x * ROWS;

    if (tid < KP * 3) kp[tid] = kpts[tid];

    // per-row edge ranges: lower_bound over sorted segment_ids
    if (tid <= ROWS) {
        int target = m0 + tid;
        int lo = 0, hi = E;
        while (lo < hi) {
            int mid = (lo + hi) >> 1;
            if (__ldg(sid + mid) < target) lo = mid + 1; else hi = mid;
        }
        bound[tid] = lo;
    }
    __syncthreads();

    const int warp = tid >> 5;
    const int lane = tid & 31;

    // ---------------- Phase 1: aggregation (warp-per-row) ----------------
    #pragma unroll
    for (int r = warp; r < ROWS; r += NWARP) {
        int m = m0 + r;
        if (m >= M) break;
        int s = bound[r];
        int e = bound[r + 1];

        float ox = __ldg(outp + m * 3 + 0);
        float oy = __ldg(outp + m * 3 + 1);
        float oz = __ldg(outp + m * 3 + 2);

        float kx = 0.f, ky = 0.f, kz = 0.f;
        if (lane < KP) {
            kx = kp[lane * 3 + 0];
            ky = kp[lane * 3 + 1];
            kz = kp[lane * 3 + 2];
        }

        float acc[KP];
        #pragma unroll
        for (int k = 0; k < KP; k++) acc[k] = 0.f;

        for (int base = s; base < e; base += 32) {
            int rem = e - base;
            int cnt = rem < 32 ? rem : 32;

            // batch-load neighbor indices: 1 coalesced LDG per 32 edges;
            // index for edge j is then available via shfl with no load chain.
            int my_ni = 0;
            if (lane < cnt) my_ni = __ldg(nbr + base + lane);

            int j = 0;
            for (; j + 4 <= cnt; j += 4) {
                int   nn[4];
                float ft[4], rx[4], ry[4], rz[4], w[4];
                #pragma unroll
                for (int u = 0; u < 4; u++)
                    nn[u] = __shfl_sync(0xffffffffu, my_ni, j + u);
                // 16 independent gathers in flight
                #pragma unroll
                for (int u = 0; u < 4; u++) {
                    ft[u] = __ldg(features + nn[u] * FDIM + lane);
                    rx[u] = __ldg(points + nn[u] * 3 + 0) - ox;
                    ry[u] = __ldg(points + nn[u] * 3 + 1) - oy;
                    rz[u] = __ldg(points + nn[u] * 3 + 2) - oz;
                }
                #pragma unroll
                for (int u = 0; u < 4; u++) {
                    float dx = rx[u] - kx, dy = ry[u] - ky, dz = rz[u] - kz;
                    float sq = fmaf(dx, dx, fmaf(dy, dy, dz * dz));
                    w[u] = fmaxf(1.f - sqrtf(sq) * INV_EXTENT, 0.f);
                }
                #pragma unroll
                for (int k = 0; k < KP; k++) {
                    #pragma unroll
                    for (int u = 0; u < 4; u++) {
                        float wk = __shfl_sync(0xffffffffu, w[u], k);
                        acc[k] = fmaf(wk, ft[u], acc[k]);
                    }
                }
            }
            for (; j < cnt; ++j) {
                int ni = __shfl_sync(0xffffffffu, my_ni, j);
                float ft = __ldg(features + ni * FDIM + lane);
                float rx = __ldg(points + ni * 3 + 0) - ox;
                float ry = __ldg(points + ni * 3 + 1) - oy;
                float rz = __ldg(points + ni * 3 + 2) - oz;
                float dx = rx - kx, dy = ry - ky, dz = rz - kz;
                float sq = fmaf(dx, dx, fmaf(dy, dy, dz * dz));
                float w  = fmaxf(1.f - sqrtf(sq) * INV_EXTENT, 0.f);
                #pragma unroll
                for (int k = 0; k < KP; k++) {
                    float wk = __shfl_sync(0xffffffffu, w, k);
                    acc[k] = fmaf(wk, ft, acc[k]);
                }
            }
        }

        #pragma unroll
        for (int k = 0; k < KP; k++)
            agg_s[r * AGG_LD + k * 32 + lane] = acc[k];
    }
    __syncthreads();

    // ---------------- Phase 2: GEMM [ROWS,480] x [480,64] ----------------
    // 256 threads: rg = tid/16 (16 groups x 2 rows), cg = tid%16 (x 4 cols)
    const int rg = tid >> 4;
    const int cg = tid & 15;

    float accc[2][4];
    #pragma unroll
    for (int i = 0; i < 2; i++)
        #pragma unroll
        for (int j = 0; j < 4; j++) accc[i][j] = 0.f;

    const float* kvp = kv + (cg << 2);

    #pragma unroll 2
    for (int kf = 0; kf < KFTOT; kf += 4) {
        float a[2][4];
        #pragma unroll
        for (int i = 0; i < 2; i++)
            *(float4*)a[i] = *(const float4*)&agg_s[(rg * 2 + i) * AGG_LD + kf];

        #pragma unroll
        for (int j = 0; j < 4; j++) {
            float4 b = __ldg((const float4*)(kvp + (kf + j) * CDIM));
            #pragma unroll
            for (int i = 0; i < 2; i++) {
                accc[i][0] = fmaf(a[i][j], b.x, accc[i][0]);
                accc[i][1] = fmaf(a[i][j], b.y, accc[i][1]);
                accc[i][2] = fmaf(a[i][j], b.z, accc[i][2]);
                accc[i][3] = fmaf(a[i][j], b.w, accc[i][3]);
            }
        }
    }

    #pragma unroll
    for (int i = 0; i < 2; i++) {
        int m = m0 + rg * 2 + i;
        if (m < M)
            *(float4*)(out + m * CDIM + (cg << 2)) =
                make_float4(accc[i][0], accc[i][1], accc[i][2], accc[i][3]);
    }
}

extern "C" void kernel_launch(void* const* d_in, const int* in_sizes, int n_in,
                              void* d_out, int out_size) {
    const float* points   = (const float*)d_in[0];
    const float* features = (const float*)d_in[1];
    const float* outp     = (const float*)d_in[2];
    const int*   nbr      = (const int*)d_in[3];
    const int*   sid      = (const int*)d_in[4];
    const float* kpts     = (const float*)d_in[5];
    const float* kv       = (const float*)d_in[6];
    float*       out      = (float*)d_out;

    int E = in_sizes[3];
    int M = out_size / CDIM;
    int blocks = (M + ROWS - 1) / ROWS;

    static bool attr_set = false;
    if (!attr_set) {
        cudaFuncSetAttribute(kpconv_fused_kernel,
                             cudaFuncAttributeMaxDynamicSharedMemorySize,
                             SMEM_BYTES);
        attr_set = true;
    }

    kpconv_fused_kernel<<<blocks, THREADS, SMEM_BYTES>>>(
        points, features, outp, nbr, sid, kpts, kv, out, M, E);
}

// round 3
// speedup vs baseline: 1.1373x; 1.0719x over previous
#include <cuda_runtime.h>

// KPConv fused kernel for GB300 (sm_103a). Round 3.
//
// R3 changes (L1-wavefront + FFMA-pipe bound per ncu):
//  - fma.rn.f32x2 (FFMA2) everywhere: halves fp32 FMA instruction count.
//  - Aggregation: batch weight computation (lane=edge, own-point gather),
//    weights staged as f32x2 pairs in SMEM; FMA phase = 8 LDS.64 + 8 FFMA2
//    per edge. No more 15-SHFL-per-edge.
//  - GEMM: 4x4 thread tiles with split-K across two 128-thread halves,
//    halving kv L1 traffic; SMEM reduction combines halves.

#define KP       15
#define FDIM     32
#define CDIM     64
#define ROWS     32
#define NWARP    8
#define THREADS  256
#define AGG_LD   484                  // 480 padded, keeps float4 alignment
#define INV_EXTENT (1.0f / 0.6f)

// dynamic smem: agg tile + per-warp weight staging (8 pairs x 32 edges x 8B)
#define AGG_BYTES (ROWS * AGG_LD * 4)
#define W2_BYTES  (NWARP * 8 * 32 * 8)
#define SMEM_BYTES (AGG_BYTES + W2_BYTES)

typedef unsigned long long ull;

__device__ __forceinline__ ull pack2(float lo, float hi) {
    ull d;
    asm("mov.b64 %0, {%1, %2};" : "=l"(d) : "f"(lo), "f"(hi));
    return d;
}
__device__ __forceinline__ void unpack2(ull s, float& lo, float& hi) {
    asm("mov.b64 {%0, %1}, %2;" : "=f"(lo), "=f"(hi) : "l"(s));
}
__device__ __forceinline__ ull ffma2(ull a, ull b, ull c) {
    ull d;
    asm("fma.rn.f32x2 %0, %1, %2, %3;" : "=l"(d) : "l"(a), "l"(b), "l"(c));
    return d;
}

__global__ __launch_bounds__(THREADS, 2) void kpconv_fused_kernel(
    const float* __restrict__ points,        // [N,3]
    const float* __restrict__ features,      // [N,32]
    const float* __restrict__ outp,          // [M,3]
    const int*   __restrict__ nbr,           // [E]
    const int*   __restrict__ sid,           // [E] sorted
    const float* __restrict__ kpts,          // [15,3]
    const float* __restrict__ kv,            // [15,32,64]
    float*       __restrict__ out,           // [M,64]
    int M, int E)
{
    extern __shared__ float smem[];
    float* agg_s = smem;                                   // [ROWS*AGG_LD]
    ull*   w2_s  = (ull*)(smem + ROWS * AGG_LD);           // [NWARP][8][32]
    __shared__ int   bound[ROWS + 1];
    __shared__ float kp[KP * 3];

    const int tid = threadIdx.x;
    const int m0  = blockIdx.x * ROWS;

    if (tid < KP * 3) kp[tid] = kpts[tid];

    if (tid <= ROWS) {
        int target = m0 + tid;
        int lo = 0, hi = E;
        while (lo < hi) {
            int mid = (lo + hi) >> 1;
            if (__ldg(sid + mid) < target) lo = mid + 1; else hi = mid;
        }
        bound[tid] = lo;
    }
    __syncthreads();

    const int warp = tid >> 5;
    const int lane = tid & 31;
    ull* wrow = w2_s + warp * (8 * 32);

    // ---------------- Phase 1: aggregation (warp-per-row) ----------------
    for (int r = warp; r < ROWS; r += NWARP) {
        int m = m0 + r;
        if (m >= M) break;
        int s = bound[r];
        int e = bound[r + 1];

        float ox = __ldg(outp + m * 3 + 0);
        float oy = __ldg(outp + m * 3 + 1);
        float oz = __ldg(outp + m * 3 + 2);

        ull acc2[8];
        #pragma unroll
        for (int p = 0; p < 8; p++) acc2[p] = 0ull;

        for (int base = s; base < e; base += 32) {
            int rem = e - base;
            int cnt = rem < 32 ? rem : 32;

            // --- weight phase: lane = edge ---
            int my_ni = 0;
            float rx = 0.f, ry = 0.f, rz = 0.f;
            if (lane < cnt) {
                my_ni = __ldg(nbr + base + lane);
                rx = __ldg(points + my_ni * 3 + 0) - ox;
                ry = __ldg(points + my_ni * 3 + 1) - oy;
                rz = __ldg(points + my_ni * 3 + 2) - oz;
            }
            float w[16];
            #pragma unroll
            for (int k = 0; k < KP; k++) {
                float dx = rx - kp[k * 3 + 0];
                float dy = ry - kp[k * 3 + 1];
                float dz = rz - kp[k * 3 + 2];
                float sq = fmaf(dx, dx, fmaf(dy, dy, dz * dz));
                w[k] = fmaxf(1.f - sqrtf(sq) * INV_EXTENT, 0.f);
            }
            w[15] = 0.f;
            #pragma unroll
            for (int p = 0; p < 8; p++)
                wrow[p * 32 + lane] = pack2(w[2 * p], w[2 * p + 1]);
            __syncwarp();

            // --- FMA phase: lane = feature channel ---
            int j = 0;
            for (; j + 4 <= cnt; j += 4) {
                int   nn[4];
                float ft[4];
                #pragma unroll
                for (int u = 0; u < 4; u++)
                    nn[u] = __shfl_sync(0xffffffffu, my_ni, j + u);
                #pragma unroll
                for (int u = 0; u < 4; u++)
                    ft[u] = __ldg(features + nn[u] * FDIM + lane);
                #pragma unroll
                for (int u = 0; u < 4; u++) {
                    ull fd = pack2(ft[u], ft[u]);
                    #pragma unroll
                    for (int p = 0; p < 8; p++)
                        acc2[p] = ffma2(fd, wrow[p * 32 + j + u], acc2[p]);
                }
            }
            for (; j < cnt; ++j) {
                int ni = __shfl_sync(0xffffffffu, my_ni, j);
                float ft = __ldg(features + ni * FDIM + lane);
                ull fd = pack2(ft, ft);
                #pragma unroll
                for (int p = 0; p < 8; p++)
                    acc2[p] = ffma2(fd, wrow[p * 32 + j], acc2[p]);
            }
            __syncwarp();   // before next batch overwrites wrow
        }

        // store accumulators: agg_s[r][k*32 + lane]
        float* arow = agg_s + r * AGG_LD;
        #pragma unroll
        for (int p = 0; p < 8; p++) {
            float lo, hi;
            unpack2(acc2[p], lo, hi);
            arow[(2 * p) * 32 + lane] = lo;
            if (2 * p + 1 < KP) arow[(2 * p + 1) * 32 + lane] = hi;
        }
    }
    __syncthreads();

    // ---------------- Phase 2: GEMM [ROWS,480] x [480,64], split-K ----------------
    // 256 threads: khalf = tid>>7 (K split), rg = (tid>>4)&7 (x4 rows), cg = tid&15 (x4 cols)
    const int khalf = tid >> 7;
    const int rg    = (tid >> 4) & 7;
    const int cg    = tid & 15;

    ull acc01[4], acc23[4];
    #pragma unroll
    for (int i = 0; i < 4; i++) { acc01[i] = 0ull; acc23[i] = 0ull; }

    const float* kvp = kv + (cg << 2);
    const int kf_lo = khalf * 240;

    for (int kf = kf_lo; kf < kf_lo + 240; kf += 4) {
        float4 a4[4];
        #pragma unroll
        for (int i = 0; i < 4; i++)
            a4[i] = *(const float4*)&agg_s[(rg * 4 + i) * AGG_LD + kf];

        #pragma unroll
        for (int jj = 0; jj < 4; jj++) {
            float4 b = __ldg((const float4*)(kvp + (kf + jj) * CDIM));
            ull b01 = pack2(b.x, b.y);
            ull b23 = pack2(b.z, b.w);
            #pragma unroll
            for (int i = 0; i < 4; i++) {
                float av = (jj == 0) ? a4[i].x : (jj == 1) ? a4[i].y
                         : (jj == 2) ? a4[i].z : a4[i].w;
                ull ad = pack2(av, av);
                acc01[i] = ffma2(ad, b01, acc01[i]);
                acc23[i] = ffma2(ad, b23, acc23[i]);
            }
        }
    }
    __syncthreads();    // all GEMM reads of agg_s complete

    // khalf==1 stores partials into reused smem, khalf==0 combines + writes out
    float* red = agg_s;     // 32*64 floats
    if (khalf == 1) {
        #pragma unroll
        for (int i = 0; i < 4; i++) {
            float x, y, z, w2;
            unpack2(acc01[i], x, y);
            unpack2(acc23[i], z, w2);
            *(float4*)&red[(rg * 4 + i) * CDIM + (cg << 2)] = make_float4(x, y, z, w2);
        }
    }
    __syncthreads();
    if (khalf == 0) {
        #pragma unroll
        for (int i = 0; i < 4; i++) {
            int m = m0 + rg * 4 + i;
            if (m < M) {
                float4 o = *(const float4*)&red[(rg * 4 + i) * CDIM + (cg << 2)];
                float x, y, z, w2;
                unpack2(acc01[i], x, y);
                unpack2(acc23[i], z, w2);
                *(float4*)(out + m * CDIM + (cg << 2)) =
                    make_float4(o.x + x, o.y + y, o.z + z, o.w + w2);
            }
        }
    }
}

extern "C" void kernel_launch(void* const* d_in, const int* in_sizes, int n_in,
                              void* d_out, int out_size) {
    const float* points   = (const float*)d_in[0];
    const float* features = (const float*)d_in[1];
    const float* outp     = (const float*)d_in[2];
    const int*   nbr      = (const int*)d_in[3];
    const int*   sid      = (const int*)d_in[4];
    const float* kpts     = (const float*)d_in[5];
    const float* kv       = (const float*)d_in[6];
    float*       out      = (float*)d_out;

    int E = in_sizes[3];
    int M = out_size / CDIM;
    int blocks = (M + ROWS - 1) / ROWS;

    static bool attr_set = false;
    if (!attr_set) {
        cudaFuncSetAttribute(kpconv_fused_kernel,
                             cudaFuncAttributeMaxDynamicSharedMemorySize,
                             SMEM_BYTES);
        attr_set = true;
    }

    kpconv_fused_kernel<<<blocks, THREADS, SMEM_BYTES>>>(
        points, features, outp, nbr, sid, kpts, kv, out, M, E);
}